// round 14
// baseline (speedup 1.0000x reference)
#include <cuda_runtime.h>
#include <cstdint>

#define L 256
#define BB 16
#define NC 8
#define LL2 (L * L)
#define NEGF (-1000000000.0f)
#define TMAIN 1024
#define NCTA (BB * NC)
#define P 33

// dynamic smem layout (floats)
#define OFF_WIN 0                 // 63*P = 2079
#define OFF_S1  2079              // 94*P = 3102
#define OFF_S2  5181              // 63*P = 2079
#define OFF_LG  7260              // 63*P = 2079
#define SM_FLOATS 9339
#define SMEM_BYTES (SM_FLOATS * 4)

__device__ float  g_bS[BB * LL2];
__device__ float  g_bE[BB * LL2];
__device__ float  g_gS[BB * LL2];
__device__ float  g_gE[BB * LL2];
__device__ int    g_lens[BB];
__device__ double g_span[NCTA];
__device__ double g_b1[NCTA], g_b2[NCTA];
__device__ unsigned long long g_ctr;

#define CLUSTER_SYNC() do { \
    asm volatile("barrier.cluster.arrive.aligned;" ::: "memory"); \
    asm volatile("barrier.cluster.wait.aligned;"   ::: "memory"); } while (0)

// 1-exp online LSE update: exp(-|v-m|) serves both branches
__device__ __forceinline__ void lse1(float& m, float& s, float v) {
    float d = v - m;
    float e = __expf(-fabsf(d));
    s = (d <= 0.f) ? (s + e) : fmaf(s, e, 1.f);
    m = fmaxf(m, v);
}

__device__ __forceinline__ int robust_len(const unsigned char* __restrict__ maskspan, int b, int lane) {
    const unsigned char* rowb = maskspan + (size_t)b * LL2;
    int c8 = 0;
    for (int j = lane; j < L; j += 32) c8 += (rowb[j] != 0) ? 1 : 0;
    #pragma unroll
    for (int o = 16; o; o >>= 1) c8 += __shfl_xor_sync(0xffffffffu, c8, o);
    int n;
    if (c8 >= 100 && rowb[0] == 1) n = c8;
    else {
        const unsigned int* rowi = ((const unsigned int*)maskspan) + (size_t)b * LL2;
        int c32 = 0;
        for (int j = lane; j < L; j += 32) c32 += (rowi[j] != 0u) ? 1 : 0;
        #pragma unroll
        for (int o = 16; o; o >>= 1) c32 += __shfl_xor_sync(0xffffffffu, c32, o);
        n = c32;
    }
    return max(1, min(L, n));
}

__global__ void __launch_bounds__(TMAIN, 1)
main_kernel(const float* __restrict__ lg_all,
            const float* __restrict__ ph_all,  const float* __restrict__ pt_all,
            const float* __restrict__ pharc_all,
            const int* __restrict__ spans_all,
            const int* __restrict__ phind_all, const int* __restrict__ ptind_all,
            const unsigned char* __restrict__ maskspan,
            float* __restrict__ out) {
    extern __shared__ float sm[];
    float* sWin   = sm + OFF_WIN;
    float* sSlab1 = sm + OFF_S1;
    float* sSlab2 = sm + OFF_S2;
    float* sLg    = sm + OFF_LG;
    __shared__ double sh_red[32];
    __shared__ int sh_n, sh_last;

    const int cb = blockIdx.x, b = cb >> 3, rank = cb & 7;
    const int tid = threadIdx.x, lane = tid & 31, wid = tid >> 5;
    const int r0 = rank * 32;

    if (wid == 0) {
        int nn = robust_len(maskspan, b, lane);
        if (lane == 0) { sh_n = nn; if (rank == 0) g_lens[b] = nn; }
    }
    __syncthreads();
    const int n = sh_n;
    const int nsteps = (n + 31) >> 5;

    const float* __restrict__ lg    = lg_all    + (size_t)b * LL2;
    const float* __restrict__ pharc = pharc_all + (size_t)b * LL2;
    const int*   __restrict__ spans = spans_all + (size_t)b * LL2;
    float* __restrict__ bS = g_bS + (size_t)b * LL2;
    float* __restrict__ bE = g_bE + (size_t)b * LL2;
    float* __restrict__ gS = g_gS + (size_t)b * LL2;
    float* __restrict__ gE = g_gE + (size_t)b * LL2;

    double accT = 0.0;

    // ======================= INSIDE =======================
    for (int s = 0; s < nsteps; ++s) {
        const int w0 = s * 32;
        // lg window tile
        for (int idx = tid; idx < 63 * 32; idx += TMAIN) {
            int ri = idx >> 5, wo = idx & 31;
            int i = r0 + ri, j = i + w0 + wo;
            sLg[ri * P + wo] = (i < n && j < n) ? __ldg(&lg[i * L + j]) : 0.f;
        }
        if (s > 0) {
            for (int idx = tid; idx < 63 * 32; idx += TMAIN) {
                int rr = idx >> 5, c = idx & 31;
                int gA = r0 + w0 + 1 + rr;
                sSlab1[rr * P + c] = (gA < n) ? __ldcg(&bS[gA * L + c]) : NEGF;
                int gB = r0 + rr;
                sSlab2[rr * P + c] = (gB < n) ? __ldcg(&bS[gB * L + c]) : NEGF;
            }
        }

        // far phase: thread-per-cell online accumulation (plain LDG, L1-cached;
        // safe: barrier.cluster.wait acquire flushes L1 each super-step)
        const int riA = tid >> 5, riB = riA + 32, wo = lane;
        const int iA = r0 + riA, iB = r0 + riB;
        const bool actA = (iA + w0 + wo < n);
        const bool actB = (iB + w0 + wo < n) && (riB + wo <= 62);
        float mA = NEGF, sA2 = 0.f, mB = NEGF, sB2 = 0.f;
        if (s > 0) {
            const int T = w0 - wo;
            if (actA) {
                const float* Lp = bS + (size_t)iA * L + wo;
                const float* Rp = bE + (size_t)(iA + w0 + wo) * L + (w0 - 1);
                #pragma unroll 4
                for (int q = 0; q < T; ++q) lse1(mA, sA2, Lp[q] + Rp[-q]);
            }
            if (actB) {
                const float* Lp = bS + (size_t)iB * L + wo;
                const float* Rp = bE + (size_t)(iB + w0 + wo) * L + (w0 - 1);
                #pragma unroll 4
                for (int q = 0; q < T; ++q) lse1(mB, sB2, Lp[q] + Rp[-q]);
            }
        }
        __syncthreads();

        // near phase: thread-per-cell wavefront, lanes = wo
        for (int u = 0; u < 32; ++u) {
            if (lane == u) {
                if (actA) sWin[riA * P + u] = (s == 0 && u == 0) ? sLg[riA * P]
                                            : (mA + __logf(sA2) + sLg[riA * P + u]);
                if (actB) sWin[riB * P + u] = (s == 0 && u == 0) ? sLg[riB * P]
                                            : (mB + __logf(sB2) + sLg[riB * P + u]);
            }
            __syncthreads();
            if (u < 31) {
                if (s == 0) {
                    if (actA && wo > u) {
                        if (2 * u >= wo - 1) lse1(mA, sA2, sWin[riA * P + u] + sWin[(riA + u + 1) * P + (wo - u - 1)]);
                        if (2 * u >  wo - 1) lse1(mA, sA2, sWin[riA * P + (wo - 1 - u)] + sWin[(riA + wo - u) * P + u]);
                    }
                    if (actB && wo > u) {
                        if (2 * u >= wo - 1) lse1(mB, sB2, sWin[riB * P + u] + sWin[(riB + u + 1) * P + (wo - u - 1)]);
                        if (2 * u >  wo - 1) lse1(mB, sB2, sWin[riB * P + (wo - 1 - u)] + sWin[(riB + wo - u) * P + u]);
                    }
                } else {
                    if (actA && wo > u) {
                        lse1(mA, sA2, sWin[riA * P + u] + sSlab1[(riA + u) * P + (wo - u - 1)]);
                        lse1(mA, sA2, sSlab2[riA * P + (wo - u - 1)] + sWin[(riA + wo - u) * P + u]);
                    }
                    if (actB && wo > u) {
                        lse1(mB, sB2, sWin[riB * P + u] + sSlab1[(riB + u) * P + (wo - u - 1)]);
                        lse1(mB, sB2, sSlab2[riB * P + (wo - u - 1)] + sWin[(riB + wo - u) * P + u]);
                    }
                }
                __syncthreads();
            }
        }

        {   // write owned rows
            int ri = tid >> 5, wc = tid & 31;
            int i = r0 + ri, w = w0 + wc;
            if (i + w < n) {
                float v = sWin[ri * P + wc];
                __stcg(&bS[i * L + w], v);
                __stcg(&bE[(i + w) * L + w], v);
            }
        }
        CLUSTER_SYNC();
    }

    const float logZ = __ldcg(&bS[n - 1]);

    // ======================= OUTSIDE =======================
    for (int s = nsteps - 1; s >= 0; --s) {
        const int w1 = s * 32;
        for (int idx = tid; idx < 63 * 32; idx += TMAIN) {
            int ri = idx >> 5, wo = idx & 31;
            int a = r0 - 31 + ri, bj = a + w1 + wo;
            sLg[ri * P + wo] = (a >= 0 && bj >= 0 && bj < n) ? __ldg(&lg[a * L + bj]) : 0.f;
        }
        for (int idx = tid; idx < 94 * 32; idx += TMAIN) {
            int rr = idx >> 5, c = idx & 31;
            int g1 = r0 + w1 - 30 + rr;
            sSlab1[rr * P + c] = (g1 >= 0 && g1 < n) ? __ldcg(&bS[g1 * L + c]) : NEGF;
            if (rr < 63) {
                int g2 = r0 - 32 + rr;
                sSlab2[rr * P + c] = (g2 >= 0 && g2 < n) ? __ldcg(&bE[g2 * L + c]) : NEGF;
            }
        }

        // far phase: thread-per-cell, lanes = ri
        const int woA = tid >> 6, woB = woA + 16;
        const int ri  = tid & 63;
        const int a   = r0 - 31 + ri;
        const int bjA = a + w1 + woA, bjB = a + w1 + woB;
        const bool actA = (ri < 63) && (a >= 0) && (bjA < n) && (ri >= 31 || ri + woA >= 31);
        const bool actB = (ri < 63) && (a >= 0) && (bjB < n) && (ri >= 31 || ri + woB >= 31);
        float mA = NEGF, sA2 = 0.f, mB = NEGF, sB2 = 0.f;
        if (actA) {
            int c1f = max(0, n - a - w1 - 32);
            int c2f = max(0, a + woA - 31);
            const float* P1a = gS + (size_t)a * L + (w1 + 32);
            const float* P1b = bS + (size_t)(bjA + 1) * L + (31 - woA);
            #pragma unroll 4
            for (int q = 0; q < c1f; ++q) lse1(mA, sA2, P1a[q] + P1b[q]);
            const float* P2a = gE + (size_t)bjA * L + (w1 + 32);
            const float* P2b = bE + (size_t)(a - 1) * L + (31 - woA);
            #pragma unroll 4
            for (int q = 0; q < c2f; ++q) lse1(mA, sA2, P2a[q] + P2b[q]);
        }
        if (actB) {
            int c1f = max(0, n - a - w1 - 32);
            int c2f = max(0, a + woB - 31);
            const float* P1a = gS + (size_t)a * L + (w1 + 32);
            const float* P1b = bS + (size_t)(bjB + 1) * L + (31 - woB);
            #pragma unroll 4
            for (int q = 0; q < c1f; ++q) lse1(mB, sB2, P1a[q] + P1b[q]);
            const float* P2a = gE + (size_t)bjB * L + (w1 + 32);
            const float* P2b = bE + (size_t)(a - 1) * L + (31 - woB);
            #pragma unroll 4
            for (int q = 0; q < c2f; ++q) lse1(mB, sB2, P2a[q] + P2b[q]);
        }
        __syncthreads();

        const int T1A = actA ? max(0, min(31 - woA, n - 1 - bjA)) : 0;
        const int T2A = actA ? min(31 - woA, a) : 0;
        const int T1B = actB ? max(0, min(31 - woB, n - 1 - bjB)) : 0;
        const int T2B = actB ? min(31 - woB, a) : 0;

        // near phase: thread-per-cell wavefront, lanes = ri
        for (int u = 31; u >= 0; --u) {
            if (woA == u && actA) {
                float al = (a == 0 && bjA == n - 1) ? 0.f : (mA + __logf(sA2));
                sWin[ri * P + u] = al + sLg[ri * P + u];
            }
            if (woB == u && actB) {
                float al = (a == 0 && bjB == n - 1) ? 0.f : (mB + __logf(sB2));
                sWin[ri * P + u] = al + sLg[ri * P + u];
            }
            __syncthreads();
            if (u > 0) {
                if (actA && woA < u) {
                    int t1 = u - woA - 1;
                    if (t1 < T1A) lse1(mA, sA2, sWin[ri * P + u] + sSlab1[(ri + woA) * P + t1]);
                    int k = u - woA;
                    if (k <= T2A) lse1(mA, sA2, sWin[(ri - k) * P + u] + sSlab2[ri * P + (k - 1)]);
                }
                if (actB && woB < u) {
                    int t1 = u - woB - 1;
                    if (t1 < T1B) lse1(mB, sB2, sWin[ri * P + u] + sSlab1[(ri + woB) * P + t1]);
                    int k = u - woB;
                    if (k <= T2B) lse1(mB, sB2, sWin[(ri - k) * P + u] + sSlab2[ri * P + (k - 1)]);
                }
                __syncthreads();
            }
        }

        {   // write owned + fused loss
            int ro = tid >> 5, wc = tid & 31;
            int aa = r0 + ro, w = w1 + wc, bj = aa + w;
            if (aa < n && bj < n) {
                float gv = sWin[(ro + 31) * P + wc];
                __stcg(&gS[aa * L + w], gv);
                __stcg(&gE[bj * L + w], gv);
                float lgv = sLg[(ro + 31) * P + wc];
                float mu = fminf(__expf((gv - lgv) + __ldcg(&bS[aa * L + w]) - logZ), 1.0f);
                float p  = 1.f / (1.f + __expf(-__ldg(&pharc[aa * L + bj])));
                float pm = p * mu;
                accT += (__ldg(&spans[aa * L + bj]) >= 2) ? (double)__logf(pm) : (double)log1pf(-pm);
            }
        }
        CLUSTER_SYNC();
    }

    // ======================= BCE slice =======================
    float f1 = 0.f, f2 = 0.f;
    {
        const float* __restrict__ ph    = ph_all    + (size_t)b * LL2;
        const float* __restrict__ pt    = pt_all    + (size_t)b * LL2;
        const int*   __restrict__ phind = phind_all + (size_t)b * LL2;
        const int*   __restrict__ ptind = ptind_all + (size_t)b * LL2;
        for (int idx = rank * TMAIN + tid; idx < n * L; idx += NC * TMAIN) {
            int j = idx & (L - 1);
            if (j < n) {
                float x = __ldg(&ph[idx]);
                f1 += fmaxf(x, 0.f) + log1pf(__expf(-fabsf(x))) - x * (float)__ldg(&phind[idx]);
                float y = __ldg(&pt[idx]);
                f2 += fmaxf(y, 0.f) + log1pf(__expf(-fabsf(y))) - y * (float)__ldg(&ptind[idx]);
            }
        }
    }

    double acc = accT;
    #pragma unroll
    for (int o = 16; o; o >>= 1) {
        acc += __shfl_down_sync(0xffffffffu, acc, o);
        f1  += __shfl_down_sync(0xffffffffu, f1, o);
        f2  += __shfl_down_sync(0xffffffffu, f2, o);
    }
    if (lane == 0) sh_red[wid] = acc;
    __syncthreads();
    if (wid == 0) {
        double v = sh_red[lane];
        #pragma unroll
        for (int o = 16; o; o >>= 1) v += __shfl_down_sync(0xffffffffu, v, o);
        if (lane == 0) g_span[cb] = v;
    }
    __syncthreads();
    if (lane == 0) sh_red[wid] = (double)f1;
    __syncthreads();
    if (wid == 0) {
        double v = sh_red[lane];
        #pragma unroll
        for (int o = 16; o; o >>= 1) v += __shfl_down_sync(0xffffffffu, v, o);
        if (lane == 0) g_b1[cb] = v;
    }
    __syncthreads();
    if (lane == 0) sh_red[wid] = (double)f2;
    __syncthreads();
    if (wid == 0) {
        double v = sh_red[lane];
        #pragma unroll
        for (int o = 16; o; o >>= 1) v += __shfl_down_sync(0xffffffffu, v, o);
        if (lane == 0) g_b2[cb] = v;
    }
    __syncthreads();

    if (tid == 0) {
        __threadfence();
        unsigned long long old = atomicAdd(&g_ctr, 1ULL);
        sh_last = ((old % (unsigned long long)NCTA) == (unsigned long long)(NCTA - 1)) ? 1 : 0;
        if (sh_last) __threadfence();
    }
    __syncthreads();
    if (sh_last && wid == 0) {
        double span = 0.0, b1 = 0.0, b2 = 0.0;
        for (int k = lane; k < NCTA; k += 32) {
            span += *((volatile double*)&g_span[k]);
            b1   += *((volatile double*)&g_b1[k]);
            b2   += *((volatile double*)&g_b2[k]);
        }
        #pragma unroll
        for (int o = 16; o; o >>= 1) {
            span += __shfl_down_sync(0xffffffffu, span, o);
            b1   += __shfl_down_sync(0xffffffffu, b1, o);
            b2   += __shfl_down_sync(0xffffffffu, b2, o);
        }
        if (lane == 0) {
            double lsum = 0.0, sq = 0.0;
            for (int bb = 0; bb < BB; ++bb) {
                double nn = (double)(*((volatile int*)&g_lens[bb]));
                lsum += nn; sq += nn * nn;
            }
            double loss = 0.1 * (-span / lsum) + 0.9 * (b1 / sq + b2 / sq);
            out[0] = (float)loss;
        }
    }
}

extern "C" void kernel_launch(void* const* d_in, const int* in_sizes, int n_in,
                              void* d_out, int out_size) {
    const float* span_logits = (const float*)d_in[0];
    const float* ph          = (const float*)d_in[1];
    const float* pt          = (const float*)d_in[2];
    const float* ph_arc      = (const float*)d_in[3];
    const int*   spans_ind   = (const int*)d_in[4];
    const int*   ph_ind      = (const int*)d_in[5];
    const int*   pt_ind      = (const int*)d_in[6];
    const unsigned char* maskspan = (const unsigned char*)d_in[8];
    (void)in_sizes; (void)n_in; (void)out_size;

    cudaFuncSetAttribute(main_kernel, cudaFuncAttributeMaxDynamicSharedMemorySize, SMEM_BYTES);

    cudaLaunchConfig_t cfg = {};
    cfg.gridDim  = dim3(NCTA, 1, 1);
    cfg.blockDim = dim3(TMAIN, 1, 1);
    cfg.dynamicSmemBytes = SMEM_BYTES;
    cfg.stream = 0;
    cudaLaunchAttribute attrs[1];
    attrs[0].id = cudaLaunchAttributeClusterDimension;
    attrs[0].val.clusterDim.x = NC;
    attrs[0].val.clusterDim.y = 1;
    attrs[0].val.clusterDim.z = 1;
    cfg.attrs = attrs;
    cfg.numAttrs = 1;
    cudaLaunchKernelEx(&cfg, main_kernel,
                       span_logits, ph, pt, ph_arc, spans_ind, ph_ind, pt_ind, maskspan,
                       (float*)d_out);
}

// round 16
// speedup vs baseline: 2.3528x; 2.3528x over previous
#include <cuda_runtime.h>
#include <cstdint>

#define L 256
#define BB 16
#define NC 8
#define LL2 (L * L)
#define NEGF (-1000000000.0f)
#define TMAIN 1024
#define NCTA (BB * NC)
#define P 33

// dynamic smem layout (floats)
#define OFF_WIN 0                 // 63*P  = 2079
#define OFF_S1  2079              // 94*P  = 3102
#define OFF_S2  5181              // 63*P  = 2079
#define OFF_LG  7260              // 63*P  = 2079
#define OFF_FAR 9339              // far-tile arena: 15386
#define SM_FLOATS 24725
#define SMEM_BYTES (SM_FLOATS * 4)

__device__ float  g_bS[BB * LL2];
__device__ float  g_bE[BB * LL2];
__device__ float  g_gS[BB * LL2];
__device__ float  g_gE[BB * LL2];
__device__ int    g_lens[BB];
__device__ double g_span[NCTA];
__device__ double g_b1[NCTA], g_b2[NCTA];
__device__ unsigned long long g_ctr;

#define CLUSTER_SYNC() do { \
    asm volatile("barrier.cluster.arrive.aligned;" ::: "memory"); \
    asm volatile("barrier.cluster.wait.aligned;"   ::: "memory"); } while (0)

// 1-exp online LSE update
__device__ __forceinline__ void lse1(float& m, float& s, float v) {
    float d = v - m;
    float e = __expf(-fabsf(d));
    s = (d <= 0.f) ? (s + e) : fmaf(s, e, 1.f);
    m = fmaxf(m, v);
}

__device__ __forceinline__ int robust_len(const unsigned char* __restrict__ maskspan, int b, int lane) {
    const unsigned char* rowb = maskspan + (size_t)b * LL2;
    int c8 = 0;
    for (int j = lane; j < L; j += 32) c8 += (rowb[j] != 0) ? 1 : 0;
    #pragma unroll
    for (int o = 16; o; o >>= 1) c8 += __shfl_xor_sync(0xffffffffu, c8, o);
    int n;
    if (c8 >= 100 && rowb[0] == 1) n = c8;
    else {
        const unsigned int* rowi = ((const unsigned int*)maskspan) + (size_t)b * LL2;
        int c32 = 0;
        for (int j = lane; j < L; j += 32) c32 += (rowi[j] != 0u) ? 1 : 0;
        #pragma unroll
        for (int o = 16; o; o >>= 1) c32 += __shfl_xor_sync(0xffffffffu, c32, o);
        n = c32;
    }
    return max(1, min(L, n));
}

__global__ void __launch_bounds__(TMAIN, 1)
main_kernel(const float* __restrict__ lg_all,
            const float* __restrict__ ph_all,  const float* __restrict__ pt_all,
            const float* __restrict__ pharc_all,
            const int* __restrict__ spans_all,
            const int* __restrict__ phind_all, const int* __restrict__ ptind_all,
            const unsigned char* __restrict__ maskspan,
            float* __restrict__ out) {
    extern __shared__ float sm[];
    float* sWin   = sm + OFF_WIN;
    float* sSlab1 = sm + OFF_S1;
    float* sSlab2 = sm + OFF_S2;
    float* sLg    = sm + OFF_LG;
    float* sFar   = sm + OFF_FAR;
    __shared__ double sh_red[32];
    __shared__ int sh_n, sh_last;

    const int cb = blockIdx.x, b = cb >> 3, rank = cb & 7;
    const int tid = threadIdx.x, lane = tid & 31, wid = tid >> 5;
    const int r0 = rank * 32;

    if (wid == 0) {
        int nn = robust_len(maskspan, b, lane);
        if (lane == 0) { sh_n = nn; if (rank == 0) g_lens[b] = nn; }
    }
    __syncthreads();
    const int n = sh_n;
    const int nsteps = (n + 31) >> 5;

    const float* __restrict__ lg    = lg_all    + (size_t)b * LL2;
    const float* __restrict__ pharc = pharc_all + (size_t)b * LL2;
    const int*   __restrict__ spans = spans_all + (size_t)b * LL2;
    float* __restrict__ bS = g_bS + (size_t)b * LL2;
    float* __restrict__ bE = g_bE + (size_t)b * LL2;
    float* __restrict__ gS = g_gS + (size_t)b * LL2;
    float* __restrict__ gE = g_gE + (size_t)b * LL2;

    double accT = 0.0;

    // ======================= INSIDE =======================
    for (int s = 0; s < nsteps; ++s) {
        const int w0 = s * 32;
        for (int idx = tid; idx < 63 * 32; idx += TMAIN) {
            int ri = idx >> 5, wo = idx & 31;
            int i = r0 + ri, j = i + w0 + wo;
            sLg[ri * P + wo] = (i < n && j < n) ? __ldg(&lg[i * L + j]) : 0.f;
        }
        if (s > 0) {
            for (int idx = tid; idx < 63 * 32; idx += TMAIN) {
                int rr = idx >> 5, c = idx & 31;
                int gA = r0 + w0 + 1 + rr;
                sSlab1[rr * P + c] = (gA < n) ? __ldcg(&bS[gA * L + c]) : NEGF;
                int gB = r0 + rr;
                sSlab2[rr * P + c] = (gB < n) ? __ldcg(&bS[gB * L + c]) : NEGF;
            }
        }

        // cell ownership (same as near phase)
        const int riA = tid >> 5, riB = riA + 32, wo = lane;
        const int iA = r0 + riA, iB = r0 + riB;
        const bool actA = (iA + w0 + wo < n);
        const bool actB = (iB + w0 + wo < n) && (riB + wo <= 62);
        float mA = NEGF, sA2 = 0.f, mB = NEGF, sB2 = 0.f;

        // ---- far phase: chunked smem-staged online accumulation ----
        if (s > 0) {
            float* LA = sFar;            // [63][65]: bS rows r0..,     cols q0..q0+63
            float* RB = sFar + 4095;     // [94][33]: bE rows r0+w0..,  cols w0-32-q0..w0-1-q0
            for (int q0 = 0; q0 < w0; q0 += 32) {
                __syncthreads();
                for (int idx = tid; idx < 63 * 64; idx += TMAIN) {
                    int rr = idx >> 6, c = idx & 63;
                    int gr = r0 + rr, gc = q0 + c;
                    LA[rr * 65 + c] = (gr < L && gc < L) ? __ldcg(&bS[gr * L + gc]) : NEGF;
                }
                for (int idx = tid; idx < 94 * 32; idx += TMAIN) {
                    int rr = idx >> 5, c = idx & 31;
                    int gr = r0 + w0 + rr, gc = (w0 - 32 - q0) + c;
                    RB[rr * 33 + c] = (gr < L && gc >= 0 && gc < L) ? __ldcg(&bE[gr * L + gc]) : NEGF;
                }
                __syncthreads();
                // term q=q0+qq: bS[i][wo+q] + bE[i+w][w0-1-q]; bound q < w0-wo
                int limq = min(32, w0 - lane - q0);
                if (actA) {
                    for (int qq = 0; qq < limq; ++qq)
                        lse1(mA, sA2, LA[riA * 65 + lane + qq] + RB[(riA + lane) * 33 + (31 - qq)]);
                }
                if (actB) {
                    for (int qq = 0; qq < limq; ++qq)
                        lse1(mB, sB2, LA[riB * 65 + lane + qq] + RB[(riB + lane) * 33 + (31 - qq)]);
                }
            }
        }
        __syncthreads();

        // ---- near phase: thread-per-cell wavefront ----
        for (int u = 0; u < 32; ++u) {
            if (lane == u) {
                if (actA) sWin[riA * P + u] = (s == 0 && u == 0) ? sLg[riA * P]
                                            : (mA + __logf(sA2) + sLg[riA * P + u]);
                if (actB) sWin[riB * P + u] = (s == 0 && u == 0) ? sLg[riB * P]
                                            : (mB + __logf(sB2) + sLg[riB * P + u]);
            }
            __syncthreads();
            if (u < 31) {
                if (s == 0) {
                    if (actA && wo > u) {
                        if (2 * u >= wo - 1) lse1(mA, sA2, sWin[riA * P + u] + sWin[(riA + u + 1) * P + (wo - u - 1)]);
                        if (2 * u >  wo - 1) lse1(mA, sA2, sWin[riA * P + (wo - 1 - u)] + sWin[(riA + wo - u) * P + u]);
                    }
                    if (actB && wo > u) {
                        if (2 * u >= wo - 1) lse1(mB, sB2, sWin[riB * P + u] + sWin[(riB + u + 1) * P + (wo - u - 1)]);
                        if (2 * u >  wo - 1) lse1(mB, sB2, sWin[riB * P + (wo - 1 - u)] + sWin[(riB + wo - u) * P + u]);
                    }
                } else {
                    if (actA && wo > u) {
                        lse1(mA, sA2, sWin[riA * P + u] + sSlab1[(riA + u) * P + (wo - u - 1)]);
                        lse1(mA, sA2, sSlab2[riA * P + (wo - u - 1)] + sWin[(riA + wo - u) * P + u]);
                    }
                    if (actB && wo > u) {
                        lse1(mB, sB2, sWin[riB * P + u] + sSlab1[(riB + u) * P + (wo - u - 1)]);
                        lse1(mB, sB2, sSlab2[riB * P + (wo - u - 1)] + sWin[(riB + wo - u) * P + u]);
                    }
                }
                __syncthreads();
            }
        }

        {   // write owned rows
            int ri = tid >> 5, wc = tid & 31;
            int i = r0 + ri, w = w0 + wc;
            if (i + w < n) {
                float v = sWin[ri * P + wc];
                __stcg(&bS[i * L + w], v);
                __stcg(&bE[(i + w) * L + w], v);
            }
        }
        CLUSTER_SYNC();
    }

    const float logZ = __ldcg(&bS[n - 1]);

    // ======================= OUTSIDE =======================
    for (int s = nsteps - 1; s >= 0; --s) {
        const int w1 = s * 32;
        for (int idx = tid; idx < 63 * 32; idx += TMAIN) {
            int ri2 = idx >> 5, wo2 = idx & 31;
            int a2 = r0 - 31 + ri2, bj2 = a2 + w1 + wo2;
            sLg[ri2 * P + wo2] = (a2 >= 0 && bj2 >= 0 && bj2 < n) ? __ldg(&lg[a2 * L + bj2]) : 0.f;
        }
        for (int idx = tid; idx < 94 * 32; idx += TMAIN) {
            int rr = idx >> 5, c = idx & 31;
            int g1 = r0 + w1 - 30 + rr;
            sSlab1[rr * P + c] = (g1 >= 0 && g1 < n) ? __ldcg(&bS[g1 * L + c]) : NEGF;
            if (rr < 63) {
                int g2 = r0 - 32 + rr;
                sSlab2[rr * P + c] = (g2 >= 0 && g2 < n) ? __ldcg(&bE[g2 * L + c]) : NEGF;
            }
        }

        // cell ownership
        const int woA = tid >> 6, woB = woA + 16;
        const int ri  = tid & 63;
        const int a   = r0 - 31 + ri;
        const int bjA = a + w1 + woA, bjB = a + w1 + woB;
        const bool actA = (ri < 63) && (a >= 0) && (bjA < n) && (ri >= 31 || ri + woA >= 31);
        const bool actB = (ri < 63) && (a >= 0) && (bjB < n) && (ri >= 31 || ri + woB >= 31);
        float mA = NEGF, sA2 = 0.f, mB = NEGF, sB2 = 0.f;

        // ---- far phase: chunked smem-staged ----
        {
            float* GA = sFar;             // [63][33]: gS rows r0-31..,     cols w1+32+q0..
            float* SB = sFar + 2079;      // [94][65]: bS rows r0+w1-30..,  cols q0..q0+63
            float* GE = sFar + 8189;      // [94][33]: gE rows r0+w1-31..,  cols w1+32+q0..
            float* EB = sFar + 11291;     // [63][65]: bE rows r0-32..,     cols q0..q0+63
            const int c1f  = (actA || actB) ? max(0, n - a - w1 - 32) : 0;
            const int c2fA = actA ? max(0, a + woA - 31) : 0;
            const int c2fB = actB ? max(0, a + woB - 31) : 0;
            int maxQ = max(n - max(0, r0 - 31) - w1 - 32, r0 + 31);
            maxQ = max(0, min(maxQ, L));
            for (int q0 = 0; q0 < maxQ; q0 += 32) {
                __syncthreads();
                for (int idx = tid; idx < 63 * 32; idx += TMAIN) {
                    int rr = idx >> 5, c = idx & 31;
                    int gr = r0 - 31 + rr, gc = w1 + 32 + q0 + c;
                    GA[rr * 33 + c] = (gr >= 0 && gr < L && gc < L) ? __ldcg(&gS[gr * L + gc]) : NEGF;
                }
                for (int idx = tid; idx < 94 * 64; idx += TMAIN) {
                    int rr = idx >> 6, c = idx & 63;
                    int gr = r0 + w1 - 30 + rr, gc = q0 + c;
                    SB[rr * 65 + c] = (gr >= 0 && gr < L && gc < L) ? __ldcg(&bS[gr * L + gc]) : NEGF;
                }
                for (int idx = tid; idx < 94 * 32; idx += TMAIN) {
                    int rr = idx >> 5, c = idx & 31;
                    int gr = r0 + w1 - 31 + rr, gc = w1 + 32 + q0 + c;
                    GE[rr * 33 + c] = (gr >= 0 && gr < L && gc < L) ? __ldcg(&gE[gr * L + gc]) : NEGF;
                }
                for (int idx = tid; idx < 63 * 64; idx += TMAIN) {
                    int rr = idx >> 6, c = idx & 63;
                    int gr = r0 - 32 + rr, gc = q0 + c;
                    EB[rr * 65 + c] = (gr >= 0 && gr < L && gc < L) ? __ldcg(&bE[gr * L + gc]) : NEGF;
                }
                __syncthreads();
                // type 1: gS[a][w1+32+q] + bS[bj+1][31-wo+q], q < c1f
                {
                    int l1 = min(32, c1f - q0);
                    for (int qq = 0; qq < l1; ++qq) {
                        float t1 = GA[ri * 33 + qq];
                        if (actA) lse1(mA, sA2, t1 + SB[(ri + woA) * 65 + (31 - woA + qq)]);
                        if (actB) lse1(mB, sB2, t1 + SB[(ri + woB) * 65 + (31 - woB + qq)]);
                    }
                }
                // type 2: gE[bj][w1+32+q] + bE[a-1][31-wo+q], q < c2f
                {
                    int l2A = min(32, c2fA - q0), l2B = min(32, c2fB - q0);
                    for (int qq = 0; qq < l2A; ++qq)
                        lse1(mA, sA2, GE[(ri + woA) * 33 + qq] + EB[ri * 65 + (31 - woA + qq)]);
                    for (int qq = 0; qq < l2B; ++qq)
                        lse1(mB, sB2, GE[(ri + woB) * 33 + qq] + EB[ri * 65 + (31 - woB + qq)]);
                }
            }
        }
        __syncthreads();

        const int T1A = actA ? max(0, min(31 - woA, n - 1 - bjA)) : 0;
        const int T2A = actA ? min(31 - woA, a) : 0;
        const int T1B = actB ? max(0, min(31 - woB, n - 1 - bjB)) : 0;
        const int T2B = actB ? min(31 - woB, a) : 0;

        // ---- near phase ----
        for (int u = 31; u >= 0; --u) {
            if (woA == u && actA) {
                float al = (a == 0 && bjA == n - 1) ? 0.f : (mA + __logf(sA2));
                sWin[ri * P + u] = al + sLg[ri * P + u];
            }
            if (woB == u && actB) {
                float al = (a == 0 && bjB == n - 1) ? 0.f : (mB + __logf(sB2));
                sWin[ri * P + u] = al + sLg[ri * P + u];
            }
            __syncthreads();
            if (u > 0) {
                if (actA && woA < u) {
                    int t1 = u - woA - 1;
                    if (t1 < T1A) lse1(mA, sA2, sWin[ri * P + u] + sSlab1[(ri + woA) * P + t1]);
                    int k = u - woA;
                    if (k <= T2A) lse1(mA, sA2, sWin[(ri - k) * P + u] + sSlab2[ri * P + (k - 1)]);
                }
                if (actB && woB < u) {
                    int t1 = u - woB - 1;
                    if (t1 < T1B) lse1(mB, sB2, sWin[ri * P + u] + sSlab1[(ri + woB) * P + t1]);
                    int k = u - woB;
                    if (k <= T2B) lse1(mB, sB2, sWin[(ri - k) * P + u] + sSlab2[ri * P + (k - 1)]);
                }
                __syncthreads();
            }
        }

        {   // write owned + fused loss
            int ro = tid >> 5, wc = tid & 31;
            int aa = r0 + ro, w = w1 + wc, bj = aa + w;
            if (aa < n && bj < n) {
                float gv = sWin[(ro + 31) * P + wc];
                __stcg(&gS[aa * L + w], gv);
                __stcg(&gE[bj * L + w], gv);
                float lgv = sLg[(ro + 31) * P + wc];
                float mu = fminf(__expf((gv - lgv) + __ldcg(&bS[aa * L + w]) - logZ), 1.0f);
                float p  = 1.f / (1.f + __expf(-__ldg(&pharc[aa * L + bj])));
                float pm = p * mu;
                accT += (__ldg(&spans[aa * L + bj]) >= 2) ? (double)__logf(pm) : (double)log1pf(-pm);
            }
        }
        CLUSTER_SYNC();
    }

    // ======================= BCE slice =======================
    float f1 = 0.f, f2 = 0.f;
    {
        const float* __restrict__ ph    = ph_all    + (size_t)b * LL2;
        const float* __restrict__ pt    = pt_all    + (size_t)b * LL2;
        const int*   __restrict__ phind = phind_all + (size_t)b * LL2;
        const int*   __restrict__ ptind = ptind_all + (size_t)b * LL2;
        for (int idx = rank * TMAIN + tid; idx < n * L; idx += NC * TMAIN) {
            int j = idx & (L - 1);
            if (j < n) {
                float x = __ldg(&ph[idx]);
                f1 += fmaxf(x, 0.f) + log1pf(__expf(-fabsf(x))) - x * (float)__ldg(&phind[idx]);
                float y = __ldg(&pt[idx]);
                f2 += fmaxf(y, 0.f) + log1pf(__expf(-fabsf(y))) - y * (float)__ldg(&ptind[idx]);
            }
        }
    }

    double acc = accT;
    #pragma unroll
    for (int o = 16; o; o >>= 1) {
        acc += __shfl_down_sync(0xffffffffu, acc, o);
        f1  += __shfl_down_sync(0xffffffffu, f1, o);
        f2  += __shfl_down_sync(0xffffffffu, f2, o);
    }
    if (lane == 0) sh_red[wid] = acc;
    __syncthreads();
    if (wid == 0) {
        double v = sh_red[lane];
        #pragma unroll
        for (int o = 16; o; o >>= 1) v += __shfl_down_sync(0xffffffffu, v, o);
        if (lane == 0) g_span[cb] = v;
    }
    __syncthreads();
    if (lane == 0) sh_red[wid] = (double)f1;
    __syncthreads();
    if (wid == 0) {
        double v = sh_red[lane];
        #pragma unroll
        for (int o = 16; o; o >>= 1) v += __shfl_down_sync(0xffffffffu, v, o);
        if (lane == 0) g_b1[cb] = v;
    }
    __syncthreads();
    if (lane == 0) sh_red[wid] = (double)f2;
    __syncthreads();
    if (wid == 0) {
        double v = sh_red[lane];
        #pragma unroll
        for (int o = 16; o; o >>= 1) v += __shfl_down_sync(0xffffffffu, v, o);
        if (lane == 0) g_b2[cb] = v;
    }
    __syncthreads();

    if (tid == 0) {
        __threadfence();
        unsigned long long old = atomicAdd(&g_ctr, 1ULL);
        sh_last = ((old % (unsigned long long)NCTA) == (unsigned long long)(NCTA - 1)) ? 1 : 0;
        if (sh_last) __threadfence();
    }
    __syncthreads();
    if (sh_last && wid == 0) {
        double span = 0.0, b1 = 0.0, b2 = 0.0;
        for (int k = lane; k < NCTA; k += 32) {
            span += *((volatile double*)&g_span[k]);
            b1   += *((volatile double*)&g_b1[k]);
            b2   += *((volatile double*)&g_b2[k]);
        }
        #pragma unroll
        for (int o = 16; o; o >>= 1) {
            span += __shfl_down_sync(0xffffffffu, span, o);
            b1   += __shfl_down_sync(0xffffffffu, b1, o);
            b2   += __shfl_down_sync(0xffffffffu, b2, o);
        }
        if (lane == 0) {
            double lsum = 0.0, sq = 0.0;
            for (int bb = 0; bb < BB; ++bb) {
                double nn = (double)(*((volatile int*)&g_lens[bb]));
                lsum += nn; sq += nn * nn;
            }
            double loss = 0.1 * (-span / lsum) + 0.9 * (b1 / sq + b2 / sq);
            out[0] = (float)loss;
        }
    }
}

extern "C" void kernel_launch(void* const* d_in, const int* in_sizes, int n_in,
                              void* d_out, int out_size) {
    const float* span_logits = (const float*)d_in[0];
    const float* ph          = (const float*)d_in[1];
    const float* pt          = (const float*)d_in[2];
    const float* ph_arc      = (const float*)d_in[3];
    const int*   spans_ind   = (const int*)d_in[4];
    const int*   ph_ind      = (const int*)d_in[5];
    const int*   pt_ind      = (const int*)d_in[6];
    const unsigned char* maskspan = (const unsigned char*)d_in[8];
    (void)in_sizes; (void)n_in; (void)out_size;

    cudaFuncSetAttribute(main_kernel, cudaFuncAttributeMaxDynamicSharedMemorySize, SMEM_BYTES);

    cudaLaunchConfig_t cfg = {};
    cfg.gridDim  = dim3(NCTA, 1, 1);
    cfg.blockDim = dim3(TMAIN, 1, 1);
    cfg.dynamicSmemBytes = SMEM_BYTES;
    cfg.stream = 0;
    cudaLaunchAttribute attrs[1];
    attrs[0].id = cudaLaunchAttributeClusterDimension;
    attrs[0].val.clusterDim.x = NC;
    attrs[0].val.clusterDim.y = 1;
    attrs[0].val.clusterDim.z = 1;
    cfg.attrs = attrs;
    cfg.numAttrs = 1;
    cudaLaunchKernelEx(&cfg, main_kernel,
                       span_logits, ph, pt, ph_arc, spans_ind, ph_ind, pt_ind, maskspan,
                       (float*)d_out);
}

// round 17
// speedup vs baseline: 2.7045x; 1.1495x over previous
#include <cuda_runtime.h>
#include <cstdint>

#define L 256
#define BB 16
#define NC 8
#define LL2 (L * L)
#define NEGF (-1000000000.0f)
#define TMAIN 1024
#define NCTA (BB * NC)
#define P 33
#define LOG2E 1.4426950408889634f

// dynamic smem layout (floats)
#define OFF_WIN 0                 // 63*P  = 2079
#define OFF_S1  2079              // 94*P  = 3102
#define OFF_S2  5181              // 63*P  = 2079
#define OFF_LG  7260              // 63*P  = 2079
#define OFF_FAR 9339              // far-tile arena: 15386
#define SM_FLOATS 24725
#define SMEM_BYTES (SM_FLOATS * 4)

__device__ float  g_bS[BB * LL2];
__device__ float  g_bE[BB * LL2];
__device__ float  g_gS[BB * LL2];
__device__ float  g_gE[BB * LL2];
__device__ int    g_lens[BB];
__device__ double g_span[NCTA];
__device__ double g_b1[NCTA], g_b2[NCTA];
__device__ unsigned long long g_ctr;

#define CLUSTER_SYNC() do { \
    asm volatile("barrier.cluster.arrive.aligned;" ::: "memory"); \
    asm volatile("barrier.cluster.wait.aligned;"   ::: "memory"); } while (0)

__device__ __forceinline__ float ex2f_(float x) {
    float r; asm("ex2.approx.ftz.f32 %0, %1;" : "=f"(r) : "f"(x)); return r;
}
__device__ __forceinline__ float lg2f_(float x) {
    float r; asm("lg2.approx.ftz.f32 %0, %1;" : "=f"(r) : "f"(x)); return r;
}

// 1-exp online LSE update (base-2 domain)
__device__ __forceinline__ void lse1(float& m, float& s, float v) {
    float d = v - m;
    float e = ex2f_(-fabsf(d));
    s = (d <= 0.f) ? (s + e) : fmaf(s, e, 1.f);
    m = fmaxf(m, v);
}

__device__ __forceinline__ int robust_len(const unsigned char* __restrict__ maskspan, int b, int lane) {
    const unsigned char* rowb = maskspan + (size_t)b * LL2;
    int c8 = 0;
    for (int j = lane; j < L; j += 32) c8 += (rowb[j] != 0) ? 1 : 0;
    #pragma unroll
    for (int o = 16; o; o >>= 1) c8 += __shfl_xor_sync(0xffffffffu, c8, o);
    int n;
    if (c8 >= 100 && rowb[0] == 1) n = c8;
    else {
        const unsigned int* rowi = ((const unsigned int*)maskspan) + (size_t)b * LL2;
        int c32 = 0;
        for (int j = lane; j < L; j += 32) c32 += (rowi[j] != 0u) ? 1 : 0;
        #pragma unroll
        for (int o = 16; o; o >>= 1) c32 += __shfl_xor_sync(0xffffffffu, c32, o);
        n = c32;
    }
    return max(1, min(L, n));
}

__global__ void __launch_bounds__(TMAIN, 1)
main_kernel(const float* __restrict__ lg_all,
            const float* __restrict__ ph_all,  const float* __restrict__ pt_all,
            const float* __restrict__ pharc_all,
            const int* __restrict__ spans_all,
            const int* __restrict__ phind_all, const int* __restrict__ ptind_all,
            const unsigned char* __restrict__ maskspan,
            float* __restrict__ out) {
    extern __shared__ float sm[];
    float* sWin   = sm + OFF_WIN;
    float* sSlab1 = sm + OFF_S1;
    float* sSlab2 = sm + OFF_S2;
    float* sLg    = sm + OFF_LG;
    float* sFar   = sm + OFF_FAR;
    __shared__ double sh_red[32];
    __shared__ int sh_n, sh_last;

    const int cb = blockIdx.x, b = cb >> 3, rank = cb & 7;
    const int tid = threadIdx.x, lane = tid & 31, wid = tid >> 5;
    const int r0 = rank * 32;

    if (wid == 0) {
        int nn = robust_len(maskspan, b, lane);
        if (lane == 0) { sh_n = nn; if (rank == 0) g_lens[b] = nn; }
    }
    __syncthreads();
    const int n = sh_n;
    const int nsteps = (n + 31) >> 5;

    const float* __restrict__ lg    = lg_all    + (size_t)b * LL2;
    const float* __restrict__ pharc = pharc_all + (size_t)b * LL2;
    const int*   __restrict__ spans = spans_all + (size_t)b * LL2;
    float* __restrict__ bS = g_bS + (size_t)b * LL2;
    float* __restrict__ bE = g_bE + (size_t)b * LL2;
    float* __restrict__ gS = g_gS + (size_t)b * LL2;
    float* __restrict__ gE = g_gE + (size_t)b * LL2;

    double accT = 0.0;

    // ======================= INSIDE =======================
    for (int s = 0; s < nsteps; ++s) {
        const int w0 = s * 32;
        for (int idx = tid; idx < 63 * 32; idx += TMAIN) {
            int ri = idx >> 5, wo = idx & 31;
            int i = r0 + ri, j = i + w0 + wo;
            sLg[ri * P + wo] = (i < n && j < n) ? (__ldg(&lg[i * L + j]) * LOG2E) : 0.f;
        }
        if (s > 0) {
            for (int idx = tid; idx < 63 * 32; idx += TMAIN) {
                int rr = idx >> 5, c = idx & 31;
                int gA = r0 + w0 + 1 + rr;
                sSlab1[rr * P + c] = (gA < n) ? __ldcg(&bS[gA * L + c]) : NEGF;
                int gB = r0 + rr;
                sSlab2[rr * P + c] = (gB < n) ? __ldcg(&bS[gB * L + c]) : NEGF;
            }
        }

        // cell ownership (same as near phase)
        const int riA = tid >> 5, riB = riA + 32, wo = lane;
        const int iA = r0 + riA, iB = r0 + riB;
        const bool actA = (iA + w0 + wo < n);
        const bool actB = (iB + w0 + wo < n) && (riB + wo <= 62);
        float mA = NEGF, sA2 = 0.f, mB = NEGF, sB2 = 0.f;

        // ---- far phase: chunked smem-staged online accumulation ----
        if (s > 0) {
            float* LA = sFar;            // [63][65]
            float* RB = sFar + 4095;     // [94][33]
            for (int q0 = 0; q0 < w0; q0 += 32) {
                __syncthreads();
                for (int idx = tid; idx < 63 * 64; idx += TMAIN) {
                    int rr = idx >> 6, c = idx & 63;
                    int gr = r0 + rr, gc = q0 + c;
                    LA[rr * 65 + c] = (gr < L && gc < L) ? __ldcg(&bS[gr * L + gc]) : NEGF;
                }
                for (int idx = tid; idx < 94 * 32; idx += TMAIN) {
                    int rr = idx >> 5, c = idx & 31;
                    int gr = r0 + w0 + rr, gc = (w0 - 32 - q0) + c;
                    RB[rr * 33 + c] = (gr < L && gc >= 0 && gc < L) ? __ldcg(&bE[gr * L + gc]) : NEGF;
                }
                __syncthreads();
                int limq = min(32, w0 - lane - q0);
                if (actA) {
                    for (int qq = 0; qq < limq; ++qq)
                        lse1(mA, sA2, LA[riA * 65 + lane + qq] + RB[(riA + lane) * 33 + (31 - qq)]);
                }
                if (actB) {
                    for (int qq = 0; qq < limq; ++qq)
                        lse1(mB, sB2, LA[riB * 65 + lane + qq] + RB[(riB + lane) * 33 + (31 - qq)]);
                }
            }
        }
        __syncthreads();

        // ---- near phase: thread-per-cell wavefront (single barrier per u) ----
        for (int u = 0; u < 32; ++u) {
            if (lane == u) {
                if (actA) sWin[riA * P + u] = (s == 0 && u == 0) ? sLg[riA * P]
                                            : (mA + lg2f_(sA2) + sLg[riA * P + u]);
                if (actB) sWin[riB * P + u] = (s == 0 && u == 0) ? sLg[riB * P]
                                            : (mB + lg2f_(sB2) + sLg[riB * P + u]);
            }
            __syncthreads();
            if (u < 31) {
                if (s == 0) {
                    if (actA && wo > u) {
                        if (2 * u >= wo - 1) lse1(mA, sA2, sWin[riA * P + u] + sWin[(riA + u + 1) * P + (wo - u - 1)]);
                        if (2 * u >  wo - 1) lse1(mA, sA2, sWin[riA * P + (wo - 1 - u)] + sWin[(riA + wo - u) * P + u]);
                    }
                    if (actB && wo > u) {
                        if (2 * u >= wo - 1) lse1(mB, sB2, sWin[riB * P + u] + sWin[(riB + u + 1) * P + (wo - u - 1)]);
                        if (2 * u >  wo - 1) lse1(mB, sB2, sWin[riB * P + (wo - 1 - u)] + sWin[(riB + wo - u) * P + u]);
                    }
                } else {
                    if (actA && wo > u) {
                        lse1(mA, sA2, sWin[riA * P + u] + sSlab1[(riA + u) * P + (wo - u - 1)]);
                        lse1(mA, sA2, sSlab2[riA * P + (wo - u - 1)] + sWin[(riA + wo - u) * P + u]);
                    }
                    if (actB && wo > u) {
                        lse1(mB, sB2, sWin[riB * P + u] + sSlab1[(riB + u) * P + (wo - u - 1)]);
                        lse1(mB, sB2, sSlab2[riB * P + (wo - u - 1)] + sWin[(riB + wo - u) * P + u]);
                    }
                }
            }
        }

        {   // write owned rows
            int ri = tid >> 5, wc = tid & 31;
            int i = r0 + ri, w = w0 + wc;
            if (i + w < n) {
                float v = sWin[ri * P + wc];
                __stcg(&bS[i * L + w], v);
                __stcg(&bE[(i + w) * L + w], v);
            }
        }
        CLUSTER_SYNC();
    }

    const float logZ = __ldcg(&bS[n - 1]);

    // ======================= OUTSIDE =======================
    for (int s = nsteps - 1; s >= 0; --s) {
        const int w1 = s * 32;
        for (int idx = tid; idx < 63 * 32; idx += TMAIN) {
            int ri2 = idx >> 5, wo2 = idx & 31;
            int a2 = r0 - 31 + ri2, bj2 = a2 + w1 + wo2;
            sLg[ri2 * P + wo2] = (a2 >= 0 && bj2 >= 0 && bj2 < n) ? (__ldg(&lg[a2 * L + bj2]) * LOG2E) : 0.f;
        }
        for (int idx = tid; idx < 94 * 32; idx += TMAIN) {
            int rr = idx >> 5, c = idx & 31;
            int g1 = r0 + w1 - 30 + rr;
            sSlab1[rr * P + c] = (g1 >= 0 && g1 < n) ? __ldcg(&bS[g1 * L + c]) : NEGF;
            if (rr < 63) {
                int g2 = r0 - 32 + rr;
                sSlab2[rr * P + c] = (g2 >= 0 && g2 < n) ? __ldcg(&bE[g2 * L + c]) : NEGF;
            }
        }

        // cell ownership
        const int woA = tid >> 6, woB = woA + 16;
        const int ri  = tid & 63;
        const int a   = r0 - 31 + ri;
        const int bjA = a + w1 + woA, bjB = a + w1 + woB;
        const bool actA = (ri < 63) && (a >= 0) && (bjA < n) && (ri >= 31 || ri + woA >= 31);
        const bool actB = (ri < 63) && (a >= 0) && (bjB < n) && (ri >= 31 || ri + woB >= 31);
        float mA = NEGF, sA2 = 0.f, mB = NEGF, sB2 = 0.f;

        // ---- far phase: chunked smem-staged ----
        {
            float* GA = sFar;             // [63][33]
            float* SB = sFar + 2079;      // [94][65]
            float* GE = sFar + 8189;      // [94][33]
            float* EB = sFar + 11291;     // [63][65]
            const int c1f  = (actA || actB) ? max(0, n - a - w1 - 32) : 0;
            const int c2fA = actA ? max(0, a + woA - 31) : 0;
            const int c2fB = actB ? max(0, a + woB - 31) : 0;
            int maxQ = max(n - max(0, r0 - 31) - w1 - 32, r0 + 31);
            maxQ = max(0, min(maxQ, L));
            for (int q0 = 0; q0 < maxQ; q0 += 32) {
                __syncthreads();
                for (int idx = tid; idx < 63 * 32; idx += TMAIN) {
                    int rr = idx >> 5, c = idx & 31;
                    int gr = r0 - 31 + rr, gc = w1 + 32 + q0 + c;
                    GA[rr * 33 + c] = (gr >= 0 && gr < L && gc < L) ? __ldcg(&gS[gr * L + gc]) : NEGF;
                }
                for (int idx = tid; idx < 94 * 64; idx += TMAIN) {
                    int rr = idx >> 6, c = idx & 63;
                    int gr = r0 + w1 - 30 + rr, gc = q0 + c;
                    SB[rr * 65 + c] = (gr >= 0 && gr < L && gc < L) ? __ldcg(&bS[gr * L + gc]) : NEGF;
                }
                for (int idx = tid; idx < 94 * 32; idx += TMAIN) {
                    int rr = idx >> 5, c = idx & 31;
                    int gr = r0 + w1 - 31 + rr, gc = w1 + 32 + q0 + c;
                    GE[rr * 33 + c] = (gr >= 0 && gr < L && gc < L) ? __ldcg(&gE[gr * L + gc]) : NEGF;
                }
                for (int idx = tid; idx < 63 * 64; idx += TMAIN) {
                    int rr = idx >> 6, c = idx & 63;
                    int gr = r0 - 32 + rr, gc = q0 + c;
                    EB[rr * 65 + c] = (gr >= 0 && gr < L && gc < L) ? __ldcg(&bE[gr * L + gc]) : NEGF;
                }
                __syncthreads();
                {
                    int l1 = min(32, c1f - q0);
                    for (int qq = 0; qq < l1; ++qq) {
                        float t1 = GA[ri * 33 + qq];
                        if (actA) lse1(mA, sA2, t1 + SB[(ri + woA) * 65 + (31 - woA + qq)]);
                        if (actB) lse1(mB, sB2, t1 + SB[(ri + woB) * 65 + (31 - woB + qq)]);
                    }
                }
                {
                    int l2A = min(32, c2fA - q0), l2B = min(32, c2fB - q0);
                    for (int qq = 0; qq < l2A; ++qq)
                        lse1(mA, sA2, GE[(ri + woA) * 33 + qq] + EB[ri * 65 + (31 - woA + qq)]);
                    for (int qq = 0; qq < l2B; ++qq)
                        lse1(mB, sB2, GE[(ri + woB) * 33 + qq] + EB[ri * 65 + (31 - woB + qq)]);
                }
            }
        }
        __syncthreads();

        const int T1A = actA ? max(0, min(31 - woA, n - 1 - bjA)) : 0;
        const int T2A = actA ? min(31 - woA, a) : 0;
        const int T1B = actB ? max(0, min(31 - woB, n - 1 - bjB)) : 0;
        const int T2B = actB ? min(31 - woB, a) : 0;

        // ---- near phase (single barrier per u) ----
        for (int u = 31; u >= 0; --u) {
            if (woA == u && actA) {
                float al = (a == 0 && bjA == n - 1) ? 0.f : (mA + lg2f_(sA2));
                sWin[ri * P + u] = al + sLg[ri * P + u];
            }
            if (woB == u && actB) {
                float al = (a == 0 && bjB == n - 1) ? 0.f : (mB + lg2f_(sB2));
                sWin[ri * P + u] = al + sLg[ri * P + u];
            }
            __syncthreads();
            if (u > 0) {
                if (actA && woA < u) {
                    int t1 = u - woA - 1;
                    if (t1 < T1A) lse1(mA, sA2, sWin[ri * P + u] + sSlab1[(ri + woA) * P + t1]);
                    int k = u - woA;
                    if (k <= T2A) lse1(mA, sA2, sWin[(ri - k) * P + u] + sSlab2[ri * P + (k - 1)]);
                }
                if (actB && woB < u) {
                    int t1 = u - woB - 1;
                    if (t1 < T1B) lse1(mB, sB2, sWin[ri * P + u] + sSlab1[(ri + woB) * P + t1]);
                    int k = u - woB;
                    if (k <= T2B) lse1(mB, sB2, sWin[(ri - k) * P + u] + sSlab2[ri * P + (k - 1)]);
                }
            }
        }

        {   // write owned + fused loss
            int ro = tid >> 5, wc = tid & 31;
            int aa = r0 + ro, w = w1 + wc, bj = aa + w;
            if (aa < n && bj < n) {
                float gv = sWin[(ro + 31) * P + wc];
                __stcg(&gS[aa * L + w], gv);
                __stcg(&gE[bj * L + w], gv);
                float lgv = sLg[(ro + 31) * P + wc];
                float mu = fminf(ex2f_((gv - lgv) + __ldcg(&bS[aa * L + w]) - logZ), 1.0f);
                float p  = 1.f / (1.f + __expf(-__ldg(&pharc[aa * L + bj])));
                float pm = p * mu;
                accT += (__ldg(&spans[aa * L + bj]) >= 2) ? (double)__logf(pm) : (double)log1pf(-pm);
            }
        }
        CLUSTER_SYNC();
    }

    // ======================= BCE slice =======================
    float f1 = 0.f, f2 = 0.f;
    {
        const float* __restrict__ ph    = ph_all    + (size_t)b * LL2;
        const float* __restrict__ pt    = pt_all    + (size_t)b * LL2;
        const int*   __restrict__ phind = phind_all + (size_t)b * LL2;
        const int*   __restrict__ ptind = ptind_all + (size_t)b * LL2;
        for (int idx = rank * TMAIN + tid; idx < n * L; idx += NC * TMAIN) {
            int j = idx & (L - 1);
            if (j < n) {
                float x = __ldg(&ph[idx]);
                f1 += fmaxf(x, 0.f) + log1pf(__expf(-fabsf(x))) - x * (float)__ldg(&phind[idx]);
                float y = __ldg(&pt[idx]);
                f2 += fmaxf(y, 0.f) + log1pf(__expf(-fabsf(y))) - y * (float)__ldg(&ptind[idx]);
            }
        }
    }

    double acc = accT;
    #pragma unroll
    for (int o = 16; o; o >>= 1) {
        acc += __shfl_down_sync(0xffffffffu, acc, o);
        f1  += __shfl_down_sync(0xffffffffu, f1, o);
        f2  += __shfl_down_sync(0xffffffffu, f2, o);
    }
    if (lane == 0) sh_red[wid] = acc;
    __syncthreads();
    if (wid == 0) {
        double v = sh_red[lane];
        #pragma unroll
        for (int o = 16; o; o >>= 1) v += __shfl_down_sync(0xffffffffu, v, o);
        if (lane == 0) g_span[cb] = v;
    }
    __syncthreads();
    if (lane == 0) sh_red[wid] = (double)f1;
    __syncthreads();
    if (wid == 0) {
        double v = sh_red[lane];
        #pragma unroll
        for (int o = 16; o; o >>= 1) v += __shfl_down_sync(0xffffffffu, v, o);
        if (lane == 0) g_b1[cb] = v;
    }
    __syncthreads();
    if (lane == 0) sh_red[wid] = (double)f2;
    __syncthreads();
    if (wid == 0) {
        double v = sh_red[lane];
        #pragma unroll
        for (int o = 16; o; o >>= 1) v += __shfl_down_sync(0xffffffffu, v, o);
        if (lane == 0) g_b2[cb] = v;
    }
    __syncthreads();

    if (tid == 0) {
        __threadfence();
        unsigned long long old = atomicAdd(&g_ctr, 1ULL);
        sh_last = ((old % (unsigned long long)NCTA) == (unsigned long long)(NCTA - 1)) ? 1 : 0;
        if (sh_last) __threadfence();
    }
    __syncthreads();
    if (sh_last && wid == 0) {
        double span = 0.0, b1 = 0.0, b2 = 0.0;
        for (int k = lane; k < NCTA; k += 32) {
            span += *((volatile double*)&g_span[k]);
            b1   += *((volatile double*)&g_b1[k]);
            b2   += *((volatile double*)&g_b2[k]);
        }
        #pragma unroll
        for (int o = 16; o; o >>= 1) {
            span += __shfl_down_sync(0xffffffffu, span, o);
            b1   += __shfl_down_sync(0xffffffffu, b1, o);
            b2   += __shfl_down_sync(0xffffffffu, b2, o);
        }
        if (lane == 0) {
            double lsum = 0.0, sq = 0.0;
            for (int bb = 0; bb < BB; ++bb) {
                double nn = (double)(*((volatile int*)&g_lens[bb]));
                lsum += nn; sq += nn * nn;
            }
            double loss = 0.1 * (-span / lsum) + 0.9 * (b1 / sq + b2 / sq);
            out[0] = (float)loss;
        }
    }
}

extern "C" void kernel_launch(void* const* d_in, const int* in_sizes, int n_in,
                              void* d_out, int out_size) {
    const float* span_logits = (const float*)d_in[0];
    const float* ph          = (const float*)d_in[1];
    const float* pt          = (const float*)d_in[2];
    const float* ph_arc      = (const float*)d_in[3];
    const int*   spans_ind   = (const int*)d_in[4];
    const int*   ph_ind      = (const int*)d_in[5];
    const int*   pt_ind      = (const int*)d_in[6];
    const unsigned char* maskspan = (const unsigned char*)d_in[8];
    (void)in_sizes; (void)n_in; (void)out_size;

    cudaFuncSetAttribute(main_kernel, cudaFuncAttributeMaxDynamicSharedMemorySize, SMEM_BYTES);

    cudaLaunchConfig_t cfg = {};
    cfg.gridDim  = dim3(NCTA, 1, 1);
    cfg.blockDim = dim3(TMAIN, 1, 1);
    cfg.dynamicSmemBytes = SMEM_BYTES;
    cfg.stream = 0;
    cudaLaunchAttribute attrs[1];
    attrs[0].id = cudaLaunchAttributeClusterDimension;
    attrs[0].val.clusterDim.x = NC;
    attrs[0].val.clusterDim.y = 1;
    attrs[0].val.clusterDim.z = 1;
    cfg.attrs = attrs;
    cfg.numAttrs = 1;
    cudaLaunchKernelEx(&cfg, main_kernel,
                       span_logits, ph, pt, ph_arc, spans_ind, ph_ind, pt_ind, maskspan,
                       (float*)d_out);
}